// round 5
// baseline (speedup 1.0000x reference)
#include <cuda_runtime.h>
#include <cstdint>

#define NB 128
#define NT 512
#define CLS 16
#define TT 2048
#define FF 128
#define HH 256
#define BZ 32
#define SLOT (BZ*HH)
#define MEMOFF ((TT+1)*SLOT)

// shared memory float offsets
#define O_WA  0                    // WA[384][64]  k-major, rows r=q*16+uu (q: i,f,o,g)
#define O_WP  24576                // WP[256][32]  rows r=p*16+uu (p=0:Wci, 1:Wcf)
#define O_WO  32768                // WO[256][17]  (pad 17) rows uu
#define O_SAB 37120                // sab[384][4]  (x | h) batch-interleaved
#define O_CB0 38656                // c buffers [256][4], double-buffered
#define O_CB1 39680
#define O_PA  40704                // PA[16][64][4]
#define O_PP  44800                // PP[16][32][4]
#define O_PO  46848                // PO[16][64]
#define O_YA  47872                // yA[64][4]
#define O_YP  48128                // yP[32][4]
#define O_BA  48256                // ba[64]
#define O_BP  48320                // bp[32]
#define O_BO  48352                // bo[16]
#define O_CNS 48368                // c_new scratch [64]
#define O_HS  48432                // h_new scratch [64]
#define SMF   48496
#define SMB   (SMF*4)

__device__ __forceinline__ float sgm(float v){ return 1.f/(1.f+__expf(-v)); }
__device__ __forceinline__ float th(float v){ return 2.f/(1.f+__expf(-2.f*v)) - 1.f; }

__device__ __forceinline__ uint32_t s2u(const void* p){
  uint32_t a;
  asm("{ .reg .u64 t; cvta.to.shared.u64 t, %1; cvt.u32.u64 %0, t; }" : "=r"(a) : "l"(p));
  return a;
}
__device__ __forceinline__ void st_cluster(uint32_t laddr, uint32_t rank, float v){
  uint32_t ra;
  asm("mapa.shared::cluster.u32 %0, %1, %2;" : "=r"(ra) : "r"(laddr), "r"(rank));
  asm volatile("st.shared::cluster.f32 [%0], %1;" :: "r"(ra), "f"(v) : "memory");
}
#define CARRIVE() asm volatile("barrier.cluster.arrive.aligned;" ::: "memory")
#define CWAIT()   asm volatile("barrier.cluster.wait.aligned;"   ::: "memory")

__global__ void zk(float* __restrict__ out){
  int i = blockIdx.x*blockDim.x + threadIdx.x;
  if (i < SLOT){ out[i]=0.f; out[MEMOFF+i]=0.f; }   // h0 = c0 = 0
}

__global__ void __launch_bounds__(NT,1) __cluster_dims__(CLS,1,1) lstm(
  const float* __restrict__ x,  const float* __restrict__ Wx,  const float* __restrict__ bx,
  const float* __restrict__ Wh, const float* __restrict__ bh,
  const float* __restrict__ Wci,const float* __restrict__ bci,
  const float* __restrict__ Wcf,const float* __restrict__ bcf,
  const float* __restrict__ Wco,const float* __restrict__ bco,
  float* __restrict__ out)
{
  extern __shared__ float sm[];
  const int tid = threadIdx.x, warp = tid>>5, lane = tid&31;
  uint32_t rank; asm("mov.u32 %0, %%cluster_ctarank;" : "=r"(rank));
  const int u0 = (int)rank*16;            // this CTA's 16 units
  const int b0 = (blockIdx.x>>4)*4;       // this cluster's 4 batches
  const uint32_t sbase = s2u(sm);

  // ---- one-time weight staging (k-major transposed) ----
  for (int i=tid; i<384*64; i+=NT){
    int k=i>>6, r=i&63, q=r>>4, uu=r&15, g=q*HH+u0+uu;
    sm[O_WA+i] = (k<FF) ? Wx[g*FF+k] : Wh[g*HH+k-FF];
  }
  for (int i=tid; i<256*32; i+=NT){
    int k=i>>5, r=i&31, p=r>>4, uu=r&15;
    sm[O_WP+i] = (p?Wcf:Wci)[(u0+uu)*HH+k];
  }
  for (int i=tid; i<256*16; i+=NT){
    int k=i>>4, r=i&15;
    sm[O_WO + k*17 + r] = Wco[(u0+r)*HH+k];
  }
  if (tid<64){ int q=tid>>4, uu=tid&15, g=q*HH+u0+uu; sm[O_BA+tid]=bx[g]+bh[g]; }
  else if (tid<96){ int r=tid-64, p=r>>4, uu=r&15; sm[O_BP+r]=(p?bcf:bci)[u0+uu]; }
  else if (tid<112){ sm[O_BO+tid-96]=bco[u0+tid-96]; }

  // zero h region of sab + both c buffers
  for (int i=tid; i<1024; i+=NT) sm[O_SAB+512+i]=0.f;
  for (int i=tid; i<2048; i+=NT) sm[O_CB0+i]=0.f;

  // stage x(0): sab[k*4+b] = x[b0+b][0][k], tid = k*4+b
  sm[O_SAB + tid] = x[((long)(b0+(tid&3))*TT + 0)*FF + (tid>>2)];

  __syncthreads();
  CARRIVE(); CWAIT();   // all CTAs initialized before any DSMEM push lands

  float* hid = out;
  float* mem = out + MEMOFF;

  for (int s=0; s<TT; s++){
    const int cbOld = (s&1) ? O_CB1 : O_CB0;
    const int cbNew = (s&1) ? O_CB0 : O_CB1;

    // ---- phase A: 64 gate rows x 4 batches, K=384; warp=k-chunk(24), lane=row, rows {lane, lane+32} ----
    float a0=0,a1=0,a2=0,a3=0,a4=0,a5=0,a6=0,a7=0;
    {
      const int kb = warp*24;
      #pragma unroll
      for (int kk=0; kk<24; kk++){
        int k = kb+kk;
        float w0 = sm[O_WA + k*64 + lane];
        float w1 = sm[O_WA + k*64 + lane + 32];
        float4 sv = *(float4*)&sm[O_SAB + k*4];
        a0+=w0*sv.x; a1+=w0*sv.y; a2+=w0*sv.z; a3+=w0*sv.w;
        a4+=w1*sv.x; a5+=w1*sv.y; a6+=w1*sv.z; a7+=w1*sv.w;
      }
    }
    *(float4*)&sm[O_PA + warp*256 + lane*4]        = make_float4(a0,a1,a2,a3);
    *(float4*)&sm[O_PA + warp*256 + (lane+32)*4]   = make_float4(a4,a5,a6,a7);

    // peepholes i,f: 32 rows x 4 batches, K=256; warp=k-chunk(16), lane=row
    float p0=0,p1=0,p2=0,p3=0;
    {
      const int kb = warp*16;
      #pragma unroll
      for (int kk=0; kk<16; kk++){
        int k = kb+kk;
        float wp = sm[O_WP + k*32 + lane];
        float4 cv = *(float4*)&sm[cbOld + k*4];
        p0+=wp*cv.x; p1+=wp*cv.y; p2+=wp*cv.z; p3+=wp*cv.w;
      }
    }
    *(float4*)&sm[O_PP + warp*128 + lane*4] = make_float4(p0,p1,p2,p3);

    // prefetch x(s+1) into a register (consumed at sync-2 window)
    float xreg = 0.f;
    if (s+1<TT) xreg = x[((long)(b0+(tid&3))*TT + (s+1))*FF + (tid>>2)];

    __syncthreads();

    // ---- cross-warp reduce ----
    if (tid<256){
      float v = sm[O_BA + (tid>>2)];
      #pragma unroll
      for (int w=0; w<16; w++) v += sm[O_PA + w*256 + tid];
      sm[O_YA + tid] = v;
    } else if (tid<384){
      int t2 = tid-256;
      float v = sm[O_BP + (t2>>2)];
      #pragma unroll
      for (int w=0; w<16; w++) v += sm[O_PP + w*128 + t2];
      sm[O_YP + t2] = v;
    }
    __syncthreads();

    // ---- gates, c_new (64 items: uu = tid>>2, b = tid&3) ----
    if (tid<64){
      int uu = tid>>2, b = tid&3;
      float yi = sm[O_YA + uu*4 + b]        + sm[O_YP + uu*4 + b];
      float yf = sm[O_YA + (16+uu)*4 + b]   + sm[O_YP + (16+uu)*4 + b];
      float yg = sm[O_YA + (48+uu)*4 + b];
      float ii = sgm(yi), ff2 = sgm(yf), gg = th(yg);
      float co = sm[cbOld + (u0+uu)*4 + b];
      float cn = ff2*co + ii*gg;
      sm[O_CNS + tid] = cn;
      mem[(long)(s+1)*SLOT + (long)(b0+b)*HH + u0+uu] = cn;
    }
    __syncthreads();

    // ---- push c_new slice to all 16 CTAs (incl. self) ----
    #pragma unroll
    for (int rep=0; rep<2; rep++){
      int id = tid + rep*NT;
      int tr = id>>6, it = id&63;
      float v = sm[O_CNS + it];
      int uu = it>>2, b = it&3;
      uint32_t la = sbase + (uint32_t)(cbNew + (u0+uu)*4 + b)*4u;
      st_cluster(la, (uint32_t)tr, v);
    }
    CARRIVE();
    if (s+1<TT) sm[O_SAB + tid] = xreg;     // x region local, safe in the window
    CWAIT();                                 // all c_new visible

    // ---- phase B: o-peephole, 16 rows x 4 batches over full c_new ----
    float q0=0, q1=0;
    {
      const int kb = warp*16, r3 = lane>>2, b3 = lane&3;
      #pragma unroll
      for (int kk=0; kk<16; kk++){
        int k = kb+kk;
        float cv = sm[cbNew + k*4 + b3];
        q0 += sm[O_WO + k*17 + r3]     * cv;
        q1 += sm[O_WO + k*17 + r3 + 8] * cv;
      }
    }
    sm[O_PO + warp*64 + lane]      = q0;
    sm[O_PO + warp*64 + lane + 32] = q1;
    __syncthreads();

    // ---- o gate, h_new ----
    if (tid<64){
      int uu = tid>>2, b = tid&3;
      float v = sm[O_YA + (32+uu)*4 + b] + sm[O_BO + uu];
      #pragma unroll
      for (int w=0; w<16; w++) v += sm[O_PO + w*64 + tid];
      float oo = sgm(v);
      float cn = sm[cbNew + (u0+uu)*4 + b];
      float hn = oo * th(cn);
      sm[O_HS + tid] = hn;
      hid[(long)(s+1)*SLOT + (long)(b0+b)*HH + u0+uu] = hn;
    }
    __syncthreads();

    // ---- push h_new slice to all 16 CTAs' sab h-region ----
    #pragma unroll
    for (int rep=0; rep<2; rep++){
      int id = tid + rep*NT;
      int tr = id>>6, it = id&63;
      float v = sm[O_HS + it];
      int uu = it>>2, b = it&3;
      uint32_t la = sbase + (uint32_t)(O_SAB + (FF + u0+uu)*4 + b)*4u;
      st_cluster(la, (uint32_t)tr, v);
    }
    CARRIVE(); CWAIT();                      // all h_new visible for next step
  }
}

extern "C" void kernel_launch(void* const* d_in, const int* in_sizes, int n_in,
                              void* d_out, int out_size) {
  cudaFuncSetAttribute(lstm, cudaFuncAttributeMaxDynamicSharedMemorySize, SMB);
  cudaFuncSetAttribute(lstm, cudaFuncAttributeNonPortableClusterSizeAllowed, 1);
  float* out = (float*)d_out;
  zk<<<32, 256>>>(out);
  lstm<<<NB, NT, SMB>>>(
    (const float*)d_in[0], (const float*)d_in[1], (const float*)d_in[2],
    (const float*)d_in[3], (const float*)d_in[4],
    (const float*)d_in[5], (const float*)d_in[6],
    (const float*)d_in[7], (const float*)d_in[8],
    (const float*)d_in[9], (const float*)d_in[10],
    out);
}